// round 4
// baseline (speedup 1.0000x reference)
#include <cuda_runtime.h>

// Problem constants
#define BB 2
#define HH 160
#define WW 192
#define DD 160
#define NN (HH * WW * DD)        // 4,915,200 voxels per batch
#define NTOT (BB * NN)           // 9,830,400
#define WD (WW * DD)

// Tile geometry
#define TH 16                    // tile h extent   (160/16 = 10)
#define TW 12                    // tile w extent   (192/12 = 16)
#define TZ 32                    // tile z extent   (160/32 = 5)
#define HALO 5                   // guaranteed in-tile when |d| < 5
#define FY (TH + 2*HALO)         // 26
#define FX (TW + 2*HALO)         // 22
#define FZ (TZ + 2*HALO)         // 42
#define FOOT (FY * FX * FZ)      // 24,024 floats
#define SMEM_BYTES (FOOT * 4)    // 96,096 B  -> 2 blocks/SM

#define NBH (HH / TH)            // 10
#define NBW (WW / TW)            // 16
#define NBZ (DD / TZ)            // 5
#define NBLK (BB * NBZ * NBH * NBW)   // 1600

__global__ __launch_bounds__(256) void spatial_deformer3d_tiled(
    const float* __restrict__ X,     // interleaved [B,H,W,D,2]
    const float* __restrict__ def,   // [B,H,W,D,3]
    float* __restrict__ out)         // [B,H,W,D,1]
{
    extern __shared__ float sm[];

    // Block decode: tw innermost so consecutive blocks share halo columns in L2.
    int bi = blockIdx.x;
    int tw = bi % NBW;
    int th = (bi / NBW) % NBH;
    int tz = (bi / (NBW * NBH)) % NBZ;
    int b  = bi / (NBW * NBH * NBZ);

    int h0 = th * TH, w0 = tw * TW, zt0 = tz * TZ;
    int fy0 = h0 - HALO, fx0 = w0 - HALO, fz0 = zt0 - HALO;

    const float* __restrict__ Xb = X + (long)b * NN * 2;

    // ---- Fill footprint (channel 0 stripped from interleaved X) ----
    // Flat index order matches smem layout: ((ly*FX + lx)*FZ + lz).
    for (int idx = threadIdx.x; idx < FOOT; idx += 256) {
        int lz = idx % FZ;
        int r  = idx / FZ;
        int lx = r % FX;
        int ly = r / FX;
        int gz = min(max(fz0 + lz, 0), DD - 1);
        int gx = min(max(fx0 + lx, 0), WW - 1);
        int gy = min(max(fy0 + ly, 0), HH - 1);
        sm[idx] = __ldg(Xb + ((gy * WW + gx) * DD + gz) * 2);
    }
    __syncthreads();

    // ---- Gather: warp = one (h,w) column x 32 consecutive z ----
    int warp = threadIdx.x >> 5;
    int lane = threadIdx.x & 31;

    for (int c = warp; c < TH * TW; c += 8) {
        int gh = h0 + c / TW;
        int gw = w0 + c % TW;
        int gz = zt0 + lane;

        int t = ((b * HH + gh) * WW + gw) * DD + gz;   // < 9.8M, fits int
        const float* dv = def + (long)t * 3;
        float dx = __ldg(dv + 0);
        float dy = __ldg(dv + 1);
        float dz = __ldg(dv + 2);

        float x = (float)gw + dx;
        float y = (float)gh + dy;
        float z = (float)gz + dz;

        int ix = (int)floorf(x);
        int iy = (int)floorf(y);
        int iz = (int)floorf(z);

        int x0 = max(0, min(WW - 1, ix));
        int x1 = max(0, min(WW - 1, ix + 1));
        int y0 = max(0, min(HH - 1, iy));
        int y1 = max(0, min(HH - 1, iy + 1));
        int z0 = max(0, min(DD - 1, iz));
        int z1 = max(0, min(DD - 1, iz + 1));

        // weights use CLIPPED integer coords, per reference
        float wx0 = (float)x1 - x;
        float wx1 = x - (float)x0;
        float wy0 = (float)y1 - y;
        float wy1 = y - (float)y0;
        float wz0 = (float)z1 - z;
        float wz1 = z - (float)z0;

        int lx0 = x0 - fx0, lx1 = x1 - fx0;
        int ly0 = y0 - fy0, ly1 = y1 - fy0;
        int lz0 = z0 - fz0, lz1 = z1 - fz0;

        float p000, p001, p010, p011, p100, p101, p110, p111;

        bool in_tile = (lx0 >= 0) & (lx1 < FX) &
                       (ly0 >= 0) & (ly1 < FY) &
                       (lz0 >= 0) & (lz1 < FZ);
        if (in_tile) {
            int r00 = (ly0 * FX + lx0) * FZ;
            int r01 = (ly0 * FX + lx1) * FZ;
            int r10 = (ly1 * FX + lx0) * FZ;
            int r11 = (ly1 * FX + lx1) * FZ;
            p000 = sm[r00 + lz0];
            p001 = sm[r00 + lz1];
            p010 = sm[r01 + lz0];
            p011 = sm[r01 + lz1];
            p100 = sm[r10 + lz0];
            p101 = sm[r10 + lz1];
            p110 = sm[r11 + lz0];
            p111 = sm[r11 + lz1];
        } else {
            // Rare (|d| >= 5): exact global fallback from interleaved X.
            int g00 = (y0 * WW + x0) * DD;
            int g01 = (y0 * WW + x1) * DD;
            int g10 = (y1 * WW + x0) * DD;
            int g11 = (y1 * WW + x1) * DD;
            p000 = __ldg(Xb + (g00 + z0) * 2);
            p001 = __ldg(Xb + (g00 + z1) * 2);
            p010 = __ldg(Xb + (g01 + z0) * 2);
            p011 = __ldg(Xb + (g01 + z1) * 2);
            p100 = __ldg(Xb + (g10 + z0) * 2);
            p101 = __ldg(Xb + (g10 + z1) * 2);
            p110 = __ldg(Xb + (g11 + z0) * 2);
            p111 = __ldg(Xb + (g11 + z1) * 2);
        }

        float v00 = fmaf(wz0, p000, wz1 * p001);
        float v01 = fmaf(wz0, p010, wz1 * p011);
        float v10 = fmaf(wz0, p100, wz1 * p101);
        float v11 = fmaf(wz0, p110, wz1 * p111);

        float v0 = fmaf(wx0, v00, wx1 * v01);
        float v1 = fmaf(wx0, v10, wx1 * v11);

        out[t] = fmaf(wy0, v0, wy1 * v1);
    }
}

extern "C" void kernel_launch(void* const* d_in, const int* in_sizes, int n_in,
                              void* d_out, int out_size) {
    const float* X   = (const float*)d_in[0];   // [2,160,192,160,2]
    const float* def = (const float*)d_in[1];   // [2,160,192,160,3]
    float* out       = (float*)d_out;

    // >48KB dynamic smem requires the opt-in attribute; host-side, idempotent,
    // graph-capture safe (no stream interaction).
    cudaFuncSetAttribute(spatial_deformer3d_tiled,
                         cudaFuncAttributeMaxDynamicSharedMemorySize, SMEM_BYTES);

    spatial_deformer3d_tiled<<<NBLK, 256, SMEM_BYTES>>>(X, def, out);
}

// round 5
// speedup vs baseline: 1.3006x; 1.3006x over previous
#include <cuda_runtime.h>

// Problem constants
#define BB 2
#define HH 160
#define WW 192
#define DD 160
#define NN (HH * WW * DD)
#define NTOT (BB * NN)

// Tile geometry: 10(h) x 12(w) x 32(z), halo 4
#define TH 10
#define TW 12
#define TZ 32
#define HALO 4
#define FY (TH + 2*HALO)         // 18
#define FX (TW + 2*HALO)         // 20
#define FZ (TZ + 2*HALO)         // 40
#define FOOT (FY * FX * FZ)      // 14,400 floats
#define SMEM_BYTES (FOOT * 4)    // 57,600 B -> 3 blocks/SM

#define NBH (HH / TH)            // 16
#define NBW (WW / TW)            // 16
#define NBZ (DD / TZ)            // 5
#define NBLK (BB * NBZ * NBH * NBW)   // 2560

#define NTHREADS 512
#define NWARPS (NTHREADS / 32)   // 16
#define NCOLS (TH * TW)          // 120 columns of 32 z-voxels

__global__ __launch_bounds__(NTHREADS) void spatial_deformer3d_tiled(
    const float* __restrict__ X,     // interleaved [B,H,W,D,2]
    const float* __restrict__ def,   // [B,H,W,D,3]
    float* __restrict__ out)         // [B,H,W,D,1]
{
    extern __shared__ float sm[];

    int bi = blockIdx.x;
    int tw = bi % NBW;
    int th = (bi / NBW) % NBH;
    int tz = (bi / (NBW * NBH)) % NBZ;
    int b  = bi / (NBW * NBH * NBZ);

    int h0 = th * TH, w0 = tw * TW, zt0 = tz * TZ;
    int fy0 = h0 - HALO, fx0 = w0 - HALO, fz0 = zt0 - HALO;

    const float* __restrict__ Xb = X + (long)b * NN * 2;

    // ---- Fill footprint: strip channel 0 from interleaved X ----
    // smem layout: ((ly*FX + lx)*FZ + lz)
#pragma unroll 4
    for (int idx = threadIdx.x; idx < FOOT; idx += NTHREADS) {
        int lz = idx % FZ;               // /40, %40: mul-shift
        int r  = idx / FZ;
        int lx = r % FX;
        int ly = r / FX;
        int gz = min(max(fz0 + lz, 0), DD - 1);
        int gx = min(max(fx0 + lx, 0), WW - 1);
        int gy = min(max(fy0 + ly, 0), HH - 1);
        sm[idx] = __ldg(Xb + ((gy * WW + gx) * DD + gz) * 2);
    }
    __syncthreads();

    // ---- Gather: warp = one (h,w) column x 32 consecutive z ----
    int warp = threadIdx.x >> 5;
    int lane = threadIdx.x & 31;

    for (int c = warp; c < NCOLS; c += NWARPS) {
        int gh = h0 + c / TW;
        int gw = w0 + c % TW;
        int gz = zt0 + lane;

        int t = ((b * HH + gh) * WW + gw) * DD + gz;
        const float* dv = def + (long)t * 3;
        float dx = __ldg(dv + 0);
        float dy = __ldg(dv + 1);
        float dz = __ldg(dv + 2);

        float x = (float)gw + dx;
        float y = (float)gh + dy;
        float z = (float)gz + dz;

        int ix = (int)floorf(x);
        int iy = (int)floorf(y);
        int iz = (int)floorf(z);

        int x0 = max(0, min(WW - 1, ix));
        int x1 = max(0, min(WW - 1, ix + 1));
        int y0 = max(0, min(HH - 1, iy));
        int y1 = max(0, min(HH - 1, iy + 1));
        int z0 = max(0, min(DD - 1, iz));
        int z1 = max(0, min(DD - 1, iz + 1));

        // weights use CLIPPED integer coords, per reference
        float wx0 = (float)x1 - x;
        float wx1 = x - (float)x0;
        float wy0 = (float)y1 - y;
        float wy1 = y - (float)y0;
        float wz0 = (float)z1 - z;
        float wz1 = z - (float)z0;

        int lx0 = x0 - fx0, lx1 = x1 - fx0;
        int ly0 = y0 - fy0, ly1 = y1 - fy0;
        int lz0 = z0 - fz0, lz1 = z1 - fz0;

        float p000, p001, p010, p011, p100, p101, p110, p111;

        bool in_tile = (lx0 >= 0) & (lx1 < FX) &
                       (ly0 >= 0) & (ly1 < FY) &
                       (lz0 >= 0) & (lz1 < FZ);
        if (in_tile) {
            int r00 = (ly0 * FX + lx0) * FZ;
            int r01 = (ly0 * FX + lx1) * FZ;
            int r10 = (ly1 * FX + lx0) * FZ;
            int r11 = (ly1 * FX + lx1) * FZ;
            p000 = sm[r00 + lz0];
            p001 = sm[r00 + lz1];
            p010 = sm[r01 + lz0];
            p011 = sm[r01 + lz1];
            p100 = sm[r10 + lz0];
            p101 = sm[r10 + lz1];
            p110 = sm[r11 + lz0];
            p111 = sm[r11 + lz1];
        } else {
            // Rare (|d| >= 4): exact global fallback from interleaved X.
            int g00 = (y0 * WW + x0) * DD;
            int g01 = (y0 * WW + x1) * DD;
            int g10 = (y1 * WW + x0) * DD;
            int g11 = (y1 * WW + x1) * DD;
            p000 = __ldg(Xb + (g00 + z0) * 2);
            p001 = __ldg(Xb + (g00 + z1) * 2);
            p010 = __ldg(Xb + (g01 + z0) * 2);
            p011 = __ldg(Xb + (g01 + z1) * 2);
            p100 = __ldg(Xb + (g10 + z0) * 2);
            p101 = __ldg(Xb + (g10 + z1) * 2);
            p110 = __ldg(Xb + (g11 + z0) * 2);
            p111 = __ldg(Xb + (g11 + z1) * 2);
        }

        float v00 = fmaf(wz0, p000, wz1 * p001);
        float v01 = fmaf(wz0, p010, wz1 * p011);
        float v10 = fmaf(wz0, p100, wz1 * p101);
        float v11 = fmaf(wz0, p110, wz1 * p111);

        float v0 = fmaf(wx0, v00, wx1 * v01);
        float v1 = fmaf(wx0, v10, wx1 * v11);

        out[t] = fmaf(wy0, v0, wy1 * v1);
    }
}

extern "C" void kernel_launch(void* const* d_in, const int* in_sizes, int n_in,
                              void* d_out, int out_size) {
    const float* X   = (const float*)d_in[0];   // [2,160,192,160,2]
    const float* def = (const float*)d_in[1];   // [2,160,192,160,3]
    float* out       = (float*)d_out;

    cudaFuncSetAttribute(spatial_deformer3d_tiled,
                         cudaFuncAttributeMaxDynamicSharedMemorySize, SMEM_BYTES);

    spatial_deformer3d_tiled<<<NBLK, NTHREADS, SMEM_BYTES>>>(X, def, out);
}

// round 7
// speedup vs baseline: 1.9946x; 1.5335x over previous
#include <cuda_runtime.h>

// Problem constants
#define BB 2
#define HH 160
#define WW 192
#define DD 160
#define NN (HH * WW * DD)

// Tile geometry: 10(h) x 12(w) x 32(z), halo 4
#define TH 10
#define TW 12
#define TZ 32
#define HALO 4
#define FY (TH + 2*HALO)         // 18
#define FX (TW + 2*HALO)         // 20
#define FZ (TZ + 2*HALO)         // 40
#define FOOT (FY * FX * FZ)      // 14,400 floats
#define SMEM_BYTES (FOOT * 4)    // 57,600 B -> 3 blocks/SM @ 512 thr = 48 warps

#define NBH (HH / TH)            // 16
#define NBW (WW / TW)            // 16
#define NBZ (DD / TZ)            // 5
#define NBLK (BB * NBZ * NBH * NBW)   // 2560

#define NTHREADS 512
#define NWARPS (NTHREADS / 32)   // 16
#define NCOLS (TH * TW)          // 120 columns of 32 z-voxels

__global__ __launch_bounds__(NTHREADS, 3) void spatial_deformer3d_tiled(
    const float* __restrict__ X,     // interleaved [B,H,W,D,2]
    const float* __restrict__ def,   // [B,H,W,D,3]
    float* __restrict__ out)         // [B,H,W,D,1]
{
    extern __shared__ float sm[];

    int bi = blockIdx.x;
    int tw = bi % NBW;
    int th = (bi / NBW) % NBH;
    int tz = (bi / (NBW * NBH)) % NBZ;
    int b  = bi / (NBW * NBH * NBZ);

    int h0 = th * TH, w0 = tw * TW, zt0 = tz * TZ;
    int fy0 = h0 - HALO, fx0 = w0 - HALO, fz0 = zt0 - HALO;

    const float* __restrict__ Xb = X + (long)b * NN * 2;

    // ---- Fill footprint: strip channel 0 from interleaved X ----
    // smem layout: ((ly*FX + lx)*FZ + lz). Halo clamped (edge replication).
    for (int idx = threadIdx.x; idx < FOOT; idx += NTHREADS) {
        int lz = idx % FZ;
        int r  = idx / FZ;
        int lx = r % FX;
        int ly = r / FX;
        int gz = min(max(fz0 + lz, 0), DD - 1);
        int gx = min(max(fx0 + lx, 0), WW - 1);
        int gy = min(max(fy0 + ly, 0), HH - 1);
        sm[idx] = __ldg(Xb + ((gy * WW + gx) * DD + gz) * 2);
    }
    __syncthreads();

    // ---- Gather: warp = one (h,w) column x 32 consecutive z ----
    int warp = threadIdx.x >> 5;
    int lane = threadIdx.x & 31;

    for (int c = warp; c < NCOLS; c += NWARPS) {
        int gh = h0 + c / TW;
        int gw = w0 + c % TW;
        int gz = zt0 + lane;

        int t = ((b * HH + gh) * WW + gw) * DD + gz;
        const float* dv = def + (long)t * 3;
        float dx = __ldg(dv + 0);
        float dy = __ldg(dv + 1);
        float dz = __ldg(dv + 2);

        float x = (float)gw + dx;
        float y = (float)gh + dy;
        float z = (float)gz + dz;

        // Float-side clamp of floor and floor+1 (exact: all values integral).
        float fxf = floorf(x);
        float fyf = floorf(y);
        float fzf = floorf(z);

        float x0f = fminf(fmaxf(fxf,       0.f), (float)(WW - 1));
        float x1f = fminf(fmaxf(fxf + 1.f, 0.f), (float)(WW - 1));
        float y0f = fminf(fmaxf(fyf,       0.f), (float)(HH - 1));
        float y1f = fminf(fmaxf(fyf + 1.f, 0.f), (float)(HH - 1));
        float z0f = fminf(fmaxf(fzf,       0.f), (float)(DD - 1));
        float z1f = fminf(fmaxf(fzf + 1.f, 0.f), (float)(DD - 1));

        // Weights from CLIPPED coords, per reference.
        float wx0 = x1f - x;
        float wx1 = x - x0f;
        float wy0 = y1f - y;
        float wy1 = y - y0f;
        float wz0 = z1f - z;
        float wz1 = z - z0f;

        int lx0 = (int)x0f - fx0;
        int lx1 = (int)x1f - fx0;
        int ly0 = (int)y0f - fy0;
        int ly1 = (int)y1f - fy0;
        int lz0 = (int)z0f - fz0;
        int lz1 = (int)z1f - fz0;

        float p000, p001, p010, p011, p100, p101, p110, p111;

        // In-footprint iff all of these are >= 0 (fold into one sign test).
        int ok = lx0 | ly0 | lz0 |
                 (FX - 1 - lx1) | (FY - 1 - ly1) | (FZ - 1 - lz1);
        if (ok >= 0) {
            int r00 = (ly0 * FX + lx0) * FZ;
            int r01 = (ly0 * FX + lx1) * FZ;
            int r10 = (ly1 * FX + lx0) * FZ;
            int r11 = (ly1 * FX + lx1) * FZ;
            p000 = sm[r00 + lz0];
            p001 = sm[r00 + lz1];
            p010 = sm[r01 + lz0];
            p011 = sm[r01 + lz1];
            p100 = sm[r10 + lz0];
            p101 = sm[r10 + lz1];
            p110 = sm[r11 + lz0];
            p111 = sm[r11 + lz1];
        } else {
            // Rare (|d| >= 4): exact global fallback from interleaved X.
            int gx0 = lx0 + fx0, gx1 = lx1 + fx0;
            int gy0 = ly0 + fy0, gy1 = ly1 + fy0;
            int gz0 = lz0 + fz0, gz1 = lz1 + fz0;
            int g00 = (gy0 * WW + gx0) * DD;
            int g01 = (gy0 * WW + gx1) * DD;
            int g10 = (gy1 * WW + gx0) * DD;
            int g11 = (gy1 * WW + gx1) * DD;
            p000 = __ldg(Xb + (g00 + gz0) * 2);
            p001 = __ldg(Xb + (g00 + gz1) * 2);
            p010 = __ldg(Xb + (g01 + gz0) * 2);
            p011 = __ldg(Xb + (g01 + gz1) * 2);
            p100 = __ldg(Xb + (g10 + gz0) * 2);
            p101 = __ldg(Xb + (g10 + gz1) * 2);
            p110 = __ldg(Xb + (g11 + gz0) * 2);
            p111 = __ldg(Xb + (g11 + gz1) * 2);
        }

        float v00 = fmaf(wz0, p000, wz1 * p001);
        float v01 = fmaf(wz0, p010, wz1 * p011);
        float v10 = fmaf(wz0, p100, wz1 * p101);
        float v11 = fmaf(wz0, p110, wz1 * p111);

        float v0 = fmaf(wx0, v00, wx1 * v01);
        float v1 = fmaf(wx0, v10, wx1 * v11);

        out[t] = fmaf(wy0, v0, wy1 * v1);
    }
}

extern "C" void kernel_launch(void* const* d_in, const int* in_sizes, int n_in,
                              void* d_out, int out_size) {
    const float* X   = (const float*)d_in[0];   // [2,160,192,160,2]
    const float* def = (const float*)d_in[1];   // [2,160,192,160,3]
    float* out       = (float*)d_out;

    cudaFuncSetAttribute(spatial_deformer3d_tiled,
                         cudaFuncAttributeMaxDynamicSharedMemorySize, SMEM_BYTES);

    spatial_deformer3d_tiled<<<NBLK, NTHREADS, SMEM_BYTES>>>(X, def, out);
}